// round 6
// baseline (speedup 1.0000x reference)
#include <cuda_runtime.h>
#include <cuda_bf16.h>
#include <math_constants.h>

#define N_NODES 50000
#define N_EDGES 800000
#define D_MODEL 128
#define N_HEADS 8
#define D_HEAD  16

// ---------------- scratch (static device globals) ---------------------------
__device__ __align__(16) float g_h[N_NODES * D_MODEL];
__device__ __align__(16) float g_qkv[N_NODES * 3 * D_MODEL];
__device__ __align__(16) float g_agg[N_NODES * D_MODEL];
__device__ int  g_cnt[N_NODES];
__device__ int  g_off[N_NODES + 1];
__device__ int  g_cursor[N_NODES];
__device__ __align__(8) int2 g_csr[N_EDGES];   // (src, eid)

// ---------------- CSR build --------------------------------------------------
__global__ void k_zero_cnt() {
    int i = blockIdx.x * blockDim.x + threadIdx.x;
    if (i < N_NODES) g_cnt[i] = 0;
}

__global__ void k_hist(const int* __restrict__ ei) {
    int i = blockIdx.x * blockDim.x + threadIdx.x;
    if (i < N_EDGES) atomicAdd(&g_cnt[ei[N_EDGES + i]], 1);
}

__global__ void k_scan() {
    __shared__ int part[1024];
    int t = threadIdx.x;
    const int CH = (N_NODES + 1023) / 1024;
    int base = t * CH;
    int s = 0;
    for (int i = 0; i < CH; i++) {
        int idx = base + i;
        if (idx < N_NODES) s += g_cnt[idx];
    }
    part[t] = s;
    __syncthreads();
    for (int o = 1; o < 1024; o <<= 1) {
        int u = (t >= o) ? part[t - o] : 0;
        __syncthreads();
        part[t] += u;
        __syncthreads();
    }
    int run = part[t] - s;
    for (int i = 0; i < CH; i++) {
        int idx = base + i;
        if (idx < N_NODES) {
            int c = g_cnt[idx];
            g_off[idx] = run;
            g_cursor[idx] = run;
            run += c;
        }
    }
    if (t == 1023) g_off[N_NODES] = N_EDGES;
}

__global__ void k_scatter(const int* __restrict__ ei) {
    int i = blockIdx.x * blockDim.x + threadIdx.x;
    if (i >= N_EDGES) return;
    int dst = ei[N_EDGES + i];
    int pos = atomicAdd(&g_cursor[dst], 1);
    g_csr[pos] = make_int2(ei[i], i);
}

// ---------------- layernorm --------------------------------------------------
__global__ void k_ln(const float* __restrict__ x,
                     const float* __restrict__ lg,
                     const float* __restrict__ lb) {
    int warp = (blockIdx.x * blockDim.x + threadIdx.x) >> 5;
    int lane = threadIdx.x & 31;
    if (warp >= N_NODES) return;
    float4 v = *(const float4*)&x[warp * D_MODEL + lane * 4];
    float s  = v.x + v.y + v.z + v.w;
    float ss = v.x*v.x + v.y*v.y + v.z*v.z + v.w*v.w;
    #pragma unroll
    for (int o = 16; o; o >>= 1) {
        s  += __shfl_xor_sync(0xFFFFFFFFu, s,  o);
        ss += __shfl_xor_sync(0xFFFFFFFFu, ss, o);
    }
    float mu  = s  * (1.0f / D_MODEL);
    float var = ss * (1.0f / D_MODEL) - mu * mu;
    float inv = rsqrtf(var + 1e-5f);
    float4 gg = *(const float4*)&lg[lane * 4];
    float4 bb = *(const float4*)&lb[lane * 4];
    float4 o;
    o.x = (v.x - mu) * inv * gg.x + bb.x;
    o.y = (v.y - mu) * inv * gg.y + bb.y;
    o.z = (v.z - mu) * inv * gg.z + bb.z;
    o.w = (v.w - mu) * inv * gg.w + bb.w;
    *(float4*)&g_h[warp * D_MODEL + lane * 4] = o;
}

// ---------------- tf32 helpers -----------------------------------------------
__device__ __forceinline__ unsigned f2tf32(float f) {
    unsigned r;
    asm("cvt.rna.tf32.f32 %0, %1;" : "=r"(r) : "f"(f));
    return r;
}

__device__ __forceinline__ void mma_tf32(float* d, const unsigned* a, const unsigned* b) {
    asm volatile(
        "mma.sync.aligned.m16n8k8.row.col.f32.tf32.tf32.f32 "
        "{%0,%1,%2,%3}, {%4,%5,%6,%7}, {%8,%9}, {%0,%1,%2,%3};"
        : "+f"(d[0]), "+f"(d[1]), "+f"(d[2]), "+f"(d[3])
        : "r"(a[0]), "r"(a[1]), "r"(a[2]), "r"(a[3]), "r"(b[0]), "r"(b[1]));
}

// ---------------- 3xTF32 GEMM ------------------------------------------------
template<int SEL>
__global__ void k_gemm_tc(const float* __restrict__ w, const float* __restrict__ b,
                          const float* __restrict__ x, float* __restrict__ outparam) {
    constexpr int WSTRIDE = (SEL == 0) ? 384 : 128;
    constexpr int OSTRIDE = (SEL == 0) ? 384 : 128;
    const float* a_src = (SEL == 0) ? g_h : g_agg;
    float* op;
    if (SEL == 0) op = g_qkv; else op = outparam;

    __shared__ float sA[128][36];
    __shared__ float sB[32][132];
    int bm = blockIdx.x, bn = blockIdx.y;
    int tid = threadIdx.x;
    int warp = tid >> 5, lane = tid & 31;
    int wm = warp & 3;
    int wn = warp >> 2;
    int lr = lane >> 2;
    int lc = lane & 3;

    float acc[2][8][4];
    #pragma unroll
    for (int t = 0; t < 2; t++)
        #pragma unroll
        for (int n = 0; n < 8; n++)
            #pragma unroll
            for (int j = 0; j < 4; j++) acc[t][n][j] = 0.f;

    for (int k0 = 0; k0 < D_MODEL; k0 += 32) {
        #pragma unroll
        for (int i = tid; i < 128 * 8; i += 256) {
            int r = i >> 3, c4 = (i & 7) * 4;
            int gr = min(bm * 128 + r, N_NODES - 1);
            float4 v = *(const float4*)&a_src[gr * D_MODEL + k0 + c4];
            *(float4*)&sA[r][c4] = v;
        }
        #pragma unroll
        for (int i = tid; i < 32 * 32; i += 256) {
            int r = i >> 5, c4 = (i & 31) * 4;
            float4 v = *(const float4*)&w[(k0 + r) * WSTRIDE + bn * 128 + c4];
            *(float4*)&sB[r][c4] = v;
        }
        __syncthreads();
        #pragma unroll
        for (int ks = 0; ks < 4; ks++) {
            int kk = ks * 8;
            unsigned ah[2][4], al[2][4];
            #pragma unroll
            for (int t = 0; t < 2; t++) {
                int r0 = wm * 32 + t * 16 + lr;
                float f0 = sA[r0][kk + lc];
                float f1 = sA[r0 + 8][kk + lc];
                float f2 = sA[r0][kk + lc + 4];
                float f3 = sA[r0 + 8][kk + lc + 4];
                ah[t][0] = f2tf32(f0); al[t][0] = f2tf32(f0 - __uint_as_float(ah[t][0]));
                ah[t][1] = f2tf32(f1); al[t][1] = f2tf32(f1 - __uint_as_float(ah[t][1]));
                ah[t][2] = f2tf32(f2); al[t][2] = f2tf32(f2 - __uint_as_float(ah[t][2]));
                ah[t][3] = f2tf32(f3); al[t][3] = f2tf32(f3 - __uint_as_float(ah[t][3]));
            }
            #pragma unroll
            for (int n = 0; n < 8; n++) {
                int c = wn * 64 + n * 8 + lr;
                float g0 = sB[kk + lc][c];
                float g1 = sB[kk + lc + 4][c];
                unsigned bh[2], bl[2];
                bh[0] = f2tf32(g0); bl[0] = f2tf32(g0 - __uint_as_float(bh[0]));
                bh[1] = f2tf32(g1); bl[1] = f2tf32(g1 - __uint_as_float(bh[1]));
                #pragma unroll
                for (int t = 0; t < 2; t++) {
                    mma_tf32(acc[t][n], al[t], bh);
                    mma_tf32(acc[t][n], ah[t], bl);
                    mma_tf32(acc[t][n], ah[t], bh);
                }
            }
        }
        __syncthreads();
    }

    #pragma unroll
    for (int t = 0; t < 2; t++) {
        #pragma unroll
        for (int n = 0; n < 8; n++) {
            int c = bn * 128 + wn * 64 + n * 8 + 2 * lc;
            float b0 = b[c], b1 = b[c + 1];
            #pragma unroll
            for (int half = 0; half < 2; half++) {
                int node = bm * 128 + wm * 32 + t * 16 + lr + half * 8;
                if (node < N_NODES) {
                    float v0 = acc[t][n][half * 2]     + b0;
                    float v1 = acc[t][n][half * 2 + 1] + b1;
                    if (SEL == 1) {
                        v0 += x[node * D_MODEL + c];
                        v1 += x[node * D_MODEL + c + 1];
                    }
                    op[node * OSTRIDE + c]     = v0;
                    op[node * OSTRIDE + c + 1] = v1;
                }
            }
        }
    }
}

// ---------------- fused edge phase: 8 lanes/edge, 4 edges in flight ----------
// lane = slot*8 + h. Lane owns head h (16 dims) of edge-slot `slot`.
// 4 independent online-softmax states per head, xor-butterfly merged at end.
__global__ void k_edge_fused(const float* __restrict__ ea) {
    int node = (blockIdx.x * blockDim.x + threadIdx.x) >> 5;
    if (node >= N_NODES) return;
    int lane = threadIdx.x & 31;
    int slot = lane >> 3;   // 0..3: which edge of the in-flight group
    int h    = lane & 7;    // head
    int beg = g_off[node], end = g_off[node + 1];

    const float* qrow = &g_qkv[node * 384 + h * 16];
    float4 q0 = *(const float4*)(qrow + 0);
    float4 q1 = *(const float4*)(qrow + 4);
    float4 q2 = *(const float4*)(qrow + 8);
    float4 q3 = *(const float4*)(qrow + 12);

    float m = -1e30f, S = 0.f;
    float4 a0 = {0,0,0,0}, a1 = {0,0,0,0}, a2 = {0,0,0,0}, a3 = {0,0,0,0};

    int e = beg + slot;
    int2 se = (e < end) ? g_csr[e] : make_int2(0, 0);
    while (e < end) {
        int en = e + 4;
        int2 se_next = (en < end) ? g_csr[en] : make_int2(0, 0);  // prefetch

        const float* kr = &g_qkv[se.x * 384 + 128 + h * 16];
        const float* vr = &g_qkv[se.x * 384 + 256 + h * 16];
        const float* ar = &ea[(size_t)se.y * D_MODEL + h * 16];
        float4 k0 = *(const float4*)(kr + 0),  k1 = *(const float4*)(kr + 4);
        float4 k2 = *(const float4*)(kr + 8),  k3 = *(const float4*)(kr + 12);
        float4 e0 = *(const float4*)(ar + 0),  e1 = *(const float4*)(ar + 4);
        float4 e2 = *(const float4*)(ar + 8),  e3 = *(const float4*)(ar + 12);
        float4 v0 = *(const float4*)(vr + 0),  v1 = *(const float4*)(vr + 4);
        float4 v2 = *(const float4*)(vr + 8),  v3 = *(const float4*)(vr + 12);

        // dot over 16 dims, 4 partial chains
        float p0 = q0.x*(k0.x+e0.x) + q0.y*(k0.y+e0.y) + q0.z*(k0.z+e0.z) + q0.w*(k0.w+e0.w);
        float p1 = q1.x*(k1.x+e1.x) + q1.y*(k1.y+e1.y) + q1.z*(k1.z+e1.z) + q1.w*(k1.w+e1.w);
        float p2 = q2.x*(k2.x+e2.x) + q2.y*(k2.y+e2.y) + q2.z*(k2.z+e2.z) + q2.w*(k2.w+e2.w);
        float p3 = q3.x*(k3.x+e3.x) + q3.y*(k3.y+e3.y) + q3.z*(k3.z+e3.z) + q3.w*(k3.w+e3.w);
        float p = ((p0 + p1) + (p2 + p3)) * 0.25f;   // DH^-0.5 = 1/4

        float mn = fmaxf(m, p);
        float sc = __expf(m - mn);
        float ex = __expf(p - mn);
        S = S * sc + ex;
        a0.x = a0.x*sc + ex*v0.x; a0.y = a0.y*sc + ex*v0.y; a0.z = a0.z*sc + ex*v0.z; a0.w = a0.w*sc + ex*v0.w;
        a1.x = a1.x*sc + ex*v1.x; a1.y = a1.y*sc + ex*v1.y; a1.z = a1.z*sc + ex*v1.z; a1.w = a1.w*sc + ex*v1.w;
        a2.x = a2.x*sc + ex*v2.x; a2.y = a2.y*sc + ex*v2.y; a2.z = a2.z*sc + ex*v2.z; a2.w = a2.w*sc + ex*v2.w;
        a3.x = a3.x*sc + ex*v3.x; a3.y = a3.y*sc + ex*v3.y; a3.z = a3.z*sc + ex*v3.z; a3.w = a3.w*sc + ex*v3.w;
        m = mn;

        se = se_next;
        e = en;
    }

    // merge the 4 slot-states (lanes h, h+8, h+16, h+24)
    #pragma unroll
    for (int off = 8; off <= 16; off <<= 1) {
        float mo = __shfl_xor_sync(0xFFFFFFFFu, m, off);
        float So = __shfl_xor_sync(0xFFFFFFFFu, S, off);
        float mn = fmaxf(m, mo);
        float s0 = __expf(m - mn);
        float s1 = __expf(mo - mn);
        S = S * s0 + So * s1;
        #define MRG(c) c = c * s0 + __shfl_xor_sync(0xFFFFFFFFu, c, off) * s1
        MRG(a0.x); MRG(a0.y); MRG(a0.z); MRG(a0.w);
        MRG(a1.x); MRG(a1.y); MRG(a1.z); MRG(a1.w);
        MRG(a2.x); MRG(a2.y); MRG(a2.z); MRG(a2.w);
        MRG(a3.x); MRG(a3.y); MRG(a3.z); MRG(a3.w);
        #undef MRG
        m = mn;
    }

    float r = 1.f / fmaxf(S, 1e-16f);
    float4 aa = (slot == 0) ? a0 : (slot == 1) ? a1 : (slot == 2) ? a2 : a3;
    float4 o; o.x = aa.x * r; o.y = aa.y * r; o.z = aa.z * r; o.w = aa.w * r;
    *(float4*)&g_agg[node * D_MODEL + h * 16 + slot * 4] = o;
}

// ---------------- launch -----------------------------------------------------
extern "C" void kernel_launch(void* const* d_in, const int* in_sizes, int n_in,
                              void* d_out, int out_size) {
    const float* x     = (const float*)d_in[0];
    const float* ea    = (const float*)d_in[1];
    const float* qkv_w = (const float*)d_in[2];
    const float* qkv_b = (const float*)d_in[3];
    const float* out_w = (const float*)d_in[4];
    const float* out_b = (const float*)d_in[5];
    const float* ln_g  = (const float*)d_in[6];
    const float* ln_b  = (const float*)d_in[7];
    const int*   ei    = (const int*)d_in[8];   // int32 [2, E]
    float* out = (float*)d_out;

    // CSR build
    k_zero_cnt<<<(N_NODES + 255) / 256, 256>>>();
    k_hist<<<(N_EDGES + 255) / 256, 256>>>(ei);
    k_scan<<<1, 1024>>>();
    k_scatter<<<(N_EDGES + 255) / 256, 256>>>(ei);

    // layernorm
    k_ln<<<(N_NODES + 7) / 8, 256>>>(x, ln_g, ln_b);

    // qkv gemm: 3xTF32 tensor cores
    {
        dim3 g((N_NODES + 127) / 128, 3);
        k_gemm_tc<0><<<g, 256>>>(qkv_w, qkv_b, nullptr, nullptr);
    }

    // fused edge phase (MLP-rich)
    k_edge_fused<<<(N_NODES + 7) / 8, 256>>>(ea);

    // out gemm + bias + residual
    {
        dim3 g((N_NODES + 127) / 128, 1);
        k_gemm_tc<1><<<g, 256>>>(out_w, out_b, x, out);
    }
}

// round 8
// speedup vs baseline: 1.0482x; 1.0482x over previous
#include <cuda_runtime.h>
#include <cuda_bf16.h>
#include <math_constants.h>

#define N_NODES 50000
#define N_EDGES 800000
#define D_MODEL 128
#define N_HEADS 8
#define D_HEAD  16

// ---------------- scratch (static device globals) ---------------------------
__device__ __align__(16) float g_h[N_NODES * D_MODEL];
__device__ __align__(16) float g_qkv[N_NODES * 3 * D_MODEL];
__device__ __align__(16) float g_agg[N_NODES * D_MODEL];
__device__ int  g_cnt[N_NODES];
__device__ int  g_off[N_NODES + 1];
__device__ int  g_cursor[N_NODES];
__device__ __align__(8) int2 g_csr[N_EDGES];   // (src, eid)

// ---------------- cache-policy load helpers ---------------------------------
// streaming (evict-first both levels): single-use data
__device__ __forceinline__ float4 ld_stream(const float* p) {
    float4 v;
    asm volatile("ld.global.cs.v4.f32 {%0,%1,%2,%3}, [%4];"
                 : "=f"(v.x), "=f"(v.y), "=f"(v.z), "=f"(v.w) : "l"(p));
    return v;
}
__device__ __forceinline__ int2 ld_stream_i2(const int2* p) {
    int2 v;
    asm volatile("ld.global.cs.v2.s32 {%0,%1}, [%2];"
                 : "=r"(v.x), "=r"(v.y) : "l"(p));
    return v;
}
// L2 evict-last via cache-policy operand (modifier form rejects v4.f32)
__device__ __forceinline__ unsigned long long mk_policy() {
    unsigned long long pol;
    asm("createpolicy.fractional.L2::evict_last.b64 %0, 1.0;" : "=l"(pol));
    return pol;
}
__device__ __forceinline__ float4 ld_resident(const float* p, unsigned long long pol) {
    float4 v;
    asm volatile("ld.global.L2::cache_hint.v4.f32 {%0,%1,%2,%3}, [%4], %5;"
                 : "=f"(v.x), "=f"(v.y), "=f"(v.z), "=f"(v.w) : "l"(p), "l"(pol));
    return v;
}

// ---------------- CSR build --------------------------------------------------
__global__ void k_zero_cnt() {
    int i = blockIdx.x * blockDim.x + threadIdx.x;
    if (i < N_NODES) g_cnt[i] = 0;
}

__global__ void k_hist(const int* __restrict__ ei) {
    int i = blockIdx.x * blockDim.x + threadIdx.x;
    if (i < N_EDGES) atomicAdd(&g_cnt[ei[N_EDGES + i]], 1);
}

__global__ void k_scan() {
    __shared__ int part[1024];
    int t = threadIdx.x;
    const int CH = (N_NODES + 1023) / 1024;
    int base = t * CH;
    int s = 0;
    for (int i = 0; i < CH; i++) {
        int idx = base + i;
        if (idx < N_NODES) s += g_cnt[idx];
    }
    part[t] = s;
    __syncthreads();
    for (int o = 1; o < 1024; o <<= 1) {
        int u = (t >= o) ? part[t - o] : 0;
        __syncthreads();
        part[t] += u;
        __syncthreads();
    }
    int run = part[t] - s;
    for (int i = 0; i < CH; i++) {
        int idx = base + i;
        if (idx < N_NODES) {
            int c = g_cnt[idx];
            g_off[idx] = run;
            g_cursor[idx] = run;
            run += c;
        }
    }
    if (t == 1023) g_off[N_NODES] = N_EDGES;
}

__global__ void k_scatter(const int* __restrict__ ei) {
    int i = blockIdx.x * blockDim.x + threadIdx.x;
    if (i >= N_EDGES) return;
    int dst = ei[N_EDGES + i];
    int pos = atomicAdd(&g_cursor[dst], 1);
    g_csr[pos] = make_int2(ei[i], i);
}

// ---------------- layernorm --------------------------------------------------
__global__ void k_ln(const float* __restrict__ x,
                     const float* __restrict__ lg,
                     const float* __restrict__ lb) {
    int warp = (blockIdx.x * blockDim.x + threadIdx.x) >> 5;
    int lane = threadIdx.x & 31;
    if (warp >= N_NODES) return;
    float4 v = *(const float4*)&x[warp * D_MODEL + lane * 4];
    float s  = v.x + v.y + v.z + v.w;
    float ss = v.x*v.x + v.y*v.y + v.z*v.z + v.w*v.w;
    #pragma unroll
    for (int o = 16; o; o >>= 1) {
        s  += __shfl_xor_sync(0xFFFFFFFFu, s,  o);
        ss += __shfl_xor_sync(0xFFFFFFFFu, ss, o);
    }
    float mu  = s  * (1.0f / D_MODEL);
    float var = ss * (1.0f / D_MODEL) - mu * mu;
    float inv = rsqrtf(var + 1e-5f);
    float4 gg = *(const float4*)&lg[lane * 4];
    float4 bb = *(const float4*)&lb[lane * 4];
    float4 o;
    o.x = (v.x - mu) * inv * gg.x + bb.x;
    o.y = (v.y - mu) * inv * gg.y + bb.y;
    o.z = (v.z - mu) * inv * gg.z + bb.z;
    o.w = (v.w - mu) * inv * gg.w + bb.w;
    *(float4*)&g_h[warp * D_MODEL + lane * 4] = o;
}

// ---------------- tf32 helpers -----------------------------------------------
__device__ __forceinline__ unsigned f2tf32(float f) {
    unsigned r;
    asm("cvt.rna.tf32.f32 %0, %1;" : "=r"(r) : "f"(f));
    return r;
}

__device__ __forceinline__ void mma_tf32(float* d, const unsigned* a, const unsigned* b) {
    asm volatile(
        "mma.sync.aligned.m16n8k8.row.col.f32.tf32.tf32.f32 "
        "{%0,%1,%2,%3}, {%4,%5,%6,%7}, {%8,%9}, {%0,%1,%2,%3};"
        : "+f"(d[0]), "+f"(d[1]), "+f"(d[2]), "+f"(d[3])
        : "r"(a[0]), "r"(a[1]), "r"(a[2]), "r"(a[3]), "r"(b[0]), "r"(b[1]));
}

// ---------------- 3xTF32 GEMM ------------------------------------------------
template<int SEL>
__global__ void k_gemm_tc(const float* __restrict__ w, const float* __restrict__ b,
                          const float* __restrict__ x, float* __restrict__ outparam) {
    constexpr int WSTRIDE = (SEL == 0) ? 384 : 128;
    constexpr int OSTRIDE = (SEL == 0) ? 384 : 128;
    const float* a_src = (SEL == 0) ? g_h : g_agg;
    float* op;
    if (SEL == 0) op = g_qkv; else op = outparam;

    __shared__ float sA[128][36];
    __shared__ float sB[32][132];
    int bm = blockIdx.x, bn = blockIdx.y;
    int tid = threadIdx.x;
    int warp = tid >> 5, lane = tid & 31;
    int wm = warp & 3;
    int wn = warp >> 2;
    int lr = lane >> 2;
    int lc = lane & 3;

    float acc[2][8][4];
    #pragma unroll
    for (int t = 0; t < 2; t++)
        #pragma unroll
        for (int n = 0; n < 8; n++)
            #pragma unroll
            for (int j = 0; j < 4; j++) acc[t][n][j] = 0.f;

    for (int k0 = 0; k0 < D_MODEL; k0 += 32) {
        #pragma unroll
        for (int i = tid; i < 128 * 8; i += 256) {
            int r = i >> 3, c4 = (i & 7) * 4;
            int gr = min(bm * 128 + r, N_NODES - 1);
            float4 v = *(const float4*)&a_src[gr * D_MODEL + k0 + c4];
            *(float4*)&sA[r][c4] = v;
        }
        #pragma unroll
        for (int i = tid; i < 32 * 32; i += 256) {
            int r = i >> 5, c4 = (i & 31) * 4;
            float4 v = *(const float4*)&w[(k0 + r) * WSTRIDE + bn * 128 + c4];
            *(float4*)&sB[r][c4] = v;
        }
        __syncthreads();
        #pragma unroll
        for (int ks = 0; ks < 4; ks++) {
            int kk = ks * 8;
            unsigned ah[2][4], al[2][4];
            #pragma unroll
            for (int t = 0; t < 2; t++) {
                int r0 = wm * 32 + t * 16 + lr;
                float f0 = sA[r0][kk + lc];
                float f1 = sA[r0 + 8][kk + lc];
                float f2 = sA[r0][kk + lc + 4];
                float f3 = sA[r0 + 8][kk + lc + 4];
                ah[t][0] = f2tf32(f0); al[t][0] = f2tf32(f0 - __uint_as_float(ah[t][0]));
                ah[t][1] = f2tf32(f1); al[t][1] = f2tf32(f1 - __uint_as_float(ah[t][1]));
                ah[t][2] = f2tf32(f2); al[t][2] = f2tf32(f2 - __uint_as_float(ah[t][2]));
                ah[t][3] = f2tf32(f3); al[t][3] = f2tf32(f3 - __uint_as_float(ah[t][3]));
            }
            #pragma unroll
            for (int n = 0; n < 8; n++) {
                int c = wn * 64 + n * 8 + lr;
                float g0 = sB[kk + lc][c];
                float g1 = sB[kk + lc + 4][c];
                unsigned bh[2], bl[2];
                bh[0] = f2tf32(g0); bl[0] = f2tf32(g0 - __uint_as_float(bh[0]));
                bh[1] = f2tf32(g1); bl[1] = f2tf32(g1 - __uint_as_float(bh[1]));
                #pragma unroll
                for (int t = 0; t < 2; t++) {
                    mma_tf32(acc[t][n], al[t], bh);
                    mma_tf32(acc[t][n], ah[t], bl);
                    mma_tf32(acc[t][n], ah[t], bh);
                }
            }
        }
        __syncthreads();
    }

    #pragma unroll
    for (int t = 0; t < 2; t++) {
        #pragma unroll
        for (int n = 0; n < 8; n++) {
            int c = bn * 128 + wn * 64 + n * 8 + 2 * lc;
            float b0 = b[c], b1 = b[c + 1];
            #pragma unroll
            for (int half = 0; half < 2; half++) {
                int node = bm * 128 + wm * 32 + t * 16 + lr + half * 8;
                if (node < N_NODES) {
                    float v0 = acc[t][n][half * 2]     + b0;
                    float v1 = acc[t][n][half * 2 + 1] + b1;
                    if (SEL == 1) {
                        v0 += x[node * D_MODEL + c];
                        v1 += x[node * D_MODEL + c + 1];
                    }
                    op[node * OSTRIDE + c]     = v0;
                    op[node * OSTRIDE + c + 1] = v1;
                }
            }
        }
    }
}

// ---------------- fused edge phase: single pass, cache-policy aware ---------
__global__ void k_edge_fused(const float* __restrict__ ea) {
    int node = (blockIdx.x * blockDim.x + threadIdx.x) >> 5;
    if (node >= N_NODES) return;
    int lane = threadIdx.x & 31;
    int beg = g_off[node], end = g_off[node + 1];
    unsigned long long pol = mk_policy();

    float4 q4 = ld_resident(&g_qkv[node * 384 + lane * 4], pol);

    float m = -CUDART_INF_F, S = 0.f;
    float ax = 0.f, ay = 0.f, az = 0.f, aw = 0.f;

    int e = beg;
    int2 se = (e < end) ? ld_stream_i2(&g_csr[e]) : make_int2(0, 0);
    while (e < end) {
        int en = e + 1;
        int2 se_next = (en < end) ? ld_stream_i2(&g_csr[en]) : make_int2(0, 0);

        float4 kv = ld_resident(&g_qkv[se.x * 384 + 128 + lane * 4], pol);
        float4 vv = ld_resident(&g_qkv[se.x * 384 + 256 + lane * 4], pol);
        float4 av = ld_stream(&ea[(size_t)se.y * D_MODEL + lane * 4]);

        float p = q4.x * (kv.x + av.x) + q4.y * (kv.y + av.y)
                + q4.z * (kv.z + av.z) + q4.w * (kv.w + av.w);
        p += __shfl_xor_sync(0xFFFFFFFFu, p, 1);
        p += __shfl_xor_sync(0xFFFFFFFFu, p, 2);   // 4-lane head group shares sum
        p *= 0.25f;                                 // DH^-0.5
        float mn = fmaxf(m, p);
        float sc = __expf(m - mn);                  // first iter: exp(-inf)=0
        float ex = __expf(p - mn);
        S  = S * sc + ex;
        ax = ax * sc + ex * vv.x;
        ay = ay * sc + ex * vv.y;
        az = az * sc + ex * vv.z;
        aw = aw * sc + ex * vv.w;
        m = mn;

        se = se_next;
        e = en;
    }
    float r = 1.f / fmaxf(S, 1e-16f);
    float4 o; o.x = ax * r; o.y = ay * r; o.z = az * r; o.w = aw * r;
    if (beg == end) { o.x = 0.f; o.y = 0.f; o.z = 0.f; o.w = 0.f; }
    *(float4*)&g_agg[node * D_MODEL + lane * 4] = o;
}

// ---------------- launch -----------------------------------------------------
extern "C" void kernel_launch(void* const* d_in, const int* in_sizes, int n_in,
                              void* d_out, int out_size) {
    const float* x     = (const float*)d_in[0];
    const float* ea    = (const float*)d_in[1];
    const float* qkv_w = (const float*)d_in[2];
    const float* qkv_b = (const float*)d_in[3];
    const float* out_w = (const float*)d_in[4];
    const float* out_b = (const float*)d_in[5];
    const float* ln_g  = (const float*)d_in[6];
    const float* ln_b  = (const float*)d_in[7];
    const int*   ei    = (const int*)d_in[8];   // int32 [2, E]
    float* out = (float*)d_out;

    // CSR build
    k_zero_cnt<<<(N_NODES + 255) / 256, 256>>>();
    k_hist<<<(N_EDGES + 255) / 256, 256>>>(ei);
    k_scan<<<1, 1024>>>();
    k_scatter<<<(N_EDGES + 255) / 256, 256>>>(ei);

    // layernorm
    k_ln<<<(N_NODES + 7) / 8, 256>>>(x, ln_g, ln_b);

    // qkv gemm: 3xTF32 tensor cores
    {
        dim3 g((N_NODES + 127) / 128, 3);
        k_gemm_tc<0><<<g, 256>>>(qkv_w, qkv_b, nullptr, nullptr);
    }

    // fused edge phase (cache-policy aware)
    k_edge_fused<<<(N_NODES + 7) / 8, 256>>>(ea);

    // out gemm + bias + residual
    {
        dim3 g((N_NODES + 127) / 128, 1);
        k_gemm_tc<1><<<g, 256>>>(out_w, out_b, x, out);
    }
}

// round 9
// speedup vs baseline: 1.1839x; 1.1295x over previous
#include <cuda_runtime.h>
#include <cuda_fp16.h>
#include <cuda_bf16.h>
#include <math_constants.h>

#define N_NODES 50000
#define N_EDGES 800000
#define D_MODEL 128
#define N_HEADS 8
#define D_HEAD  16

// ---------------- scratch (static device globals) ---------------------------
__device__ __align__(16) float  g_h[N_NODES * D_MODEL];      // layernormed x
__device__ __align__(16) float  g_q[N_NODES * D_MODEL];      // q fp32
__device__ __align__(16) __half g_kv[N_NODES * 256];         // k/v fp16 interleaved
__device__ __align__(16) float  g_agg[N_NODES * D_MODEL];
__device__ int  g_cnt[N_NODES];
__device__ int  g_off[N_NODES + 1];
__device__ int  g_cursor[N_NODES];
__device__ __align__(8) int2 g_csr[N_EDGES];   // (src, eid)

// ---------------- cache-policy load helpers ---------------------------------
__device__ __forceinline__ float4 ld_stream(const float* p) {
    float4 v;
    asm volatile("ld.global.cs.v4.f32 {%0,%1,%2,%3}, [%4];"
                 : "=f"(v.x), "=f"(v.y), "=f"(v.z), "=f"(v.w) : "l"(p));
    return v;
}
__device__ __forceinline__ int2 ld_stream_i2(const int2* p) {
    int2 v;
    asm volatile("ld.global.cs.v2.s32 {%0,%1}, [%2];"
                 : "=r"(v.x), "=r"(v.y) : "l"(p));
    return v;
}
__device__ __forceinline__ unsigned long long mk_policy() {
    unsigned long long pol;
    asm("createpolicy.fractional.L2::evict_last.b64 %0, 1.0;" : "=l"(pol));
    return pol;
}
__device__ __forceinline__ uint4 ld_resident_u4(const void* p, unsigned long long pol) {
    uint4 v;
    asm volatile("ld.global.L2::cache_hint.v4.u32 {%0,%1,%2,%3}, [%4], %5;"
                 : "=r"(v.x), "=r"(v.y), "=r"(v.z), "=r"(v.w) : "l"(p), "l"(pol));
    return v;
}

// ---------------- CSR build --------------------------------------------------
__global__ void k_zero_cnt() {
    int i = blockIdx.x * blockDim.x + threadIdx.x;
    if (i < N_NODES) g_cnt[i] = 0;
}

__global__ void k_hist(const int* __restrict__ ei) {
    int i = blockIdx.x * blockDim.x + threadIdx.x;
    if (i < N_EDGES) atomicAdd(&g_cnt[ei[N_EDGES + i]], 1);
}

__global__ void k_scan() {
    __shared__ int part[1024];
    int t = threadIdx.x;
    const int CH = (N_NODES + 1023) / 1024;
    int base = t * CH;
    int s = 0;
    for (int i = 0; i < CH; i++) {
        int idx = base + i;
        if (idx < N_NODES) s += g_cnt[idx];
    }
    part[t] = s;
    __syncthreads();
    for (int o = 1; o < 1024; o <<= 1) {
        int u = (t >= o) ? part[t - o] : 0;
        __syncthreads();
        part[t] += u;
        __syncthreads();
    }
    int run = part[t] - s;
    for (int i = 0; i < CH; i++) {
        int idx = base + i;
        if (idx < N_NODES) {
            int c = g_cnt[idx];
            g_off[idx] = run;
            g_cursor[idx] = run;
            run += c;
        }
    }
    if (t == 1023) g_off[N_NODES] = N_EDGES;
}

__global__ void k_scatter(const int* __restrict__ ei) {
    int i = blockIdx.x * blockDim.x + threadIdx.x;
    if (i >= N_EDGES) return;
    int dst = ei[N_EDGES + i];
    int pos = atomicAdd(&g_cursor[dst], 1);
    g_csr[pos] = make_int2(ei[i], i);
}

// ---------------- layernorm --------------------------------------------------
__global__ void k_ln(const float* __restrict__ x,
                     const float* __restrict__ lg,
                     const float* __restrict__ lb) {
    int warp = (blockIdx.x * blockDim.x + threadIdx.x) >> 5;
    int lane = threadIdx.x & 31;
    if (warp >= N_NODES) return;
    float4 v = *(const float4*)&x[warp * D_MODEL + lane * 4];
    float s  = v.x + v.y + v.z + v.w;
    float ss = v.x*v.x + v.y*v.y + v.z*v.z + v.w*v.w;
    #pragma unroll
    for (int o = 16; o; o >>= 1) {
        s  += __shfl_xor_sync(0xFFFFFFFFu, s,  o);
        ss += __shfl_xor_sync(0xFFFFFFFFu, ss, o);
    }
    float mu  = s  * (1.0f / D_MODEL);
    float var = ss * (1.0f / D_MODEL) - mu * mu;
    float inv = rsqrtf(var + 1e-5f);
    float4 gg = *(const float4*)&lg[lane * 4];
    float4 bb = *(const float4*)&lb[lane * 4];
    float4 o;
    o.x = (v.x - mu) * inv * gg.x + bb.x;
    o.y = (v.y - mu) * inv * gg.y + bb.y;
    o.z = (v.z - mu) * inv * gg.z + bb.z;
    o.w = (v.w - mu) * inv * gg.w + bb.w;
    *(float4*)&g_h[warp * D_MODEL + lane * 4] = o;
}

// ---------------- tf32 helpers -----------------------------------------------
__device__ __forceinline__ unsigned f2tf32(float f) {
    unsigned r;
    asm("cvt.rna.tf32.f32 %0, %1;" : "=r"(r) : "f"(f));
    return r;
}

__device__ __forceinline__ void mma_tf32(float* d, const unsigned* a, const unsigned* b) {
    asm volatile(
        "mma.sync.aligned.m16n8k8.row.col.f32.tf32.tf32.f32 "
        "{%0,%1,%2,%3}, {%4,%5,%6,%7}, {%8,%9}, {%0,%1,%2,%3};"
        : "+f"(d[0]), "+f"(d[1]), "+f"(d[2]), "+f"(d[3])
        : "r"(a[0]), "r"(a[1]), "r"(a[2]), "r"(a[3]), "r"(b[0]), "r"(b[1]));
}

// ---------------- 3xTF32 GEMM ------------------------------------------------
// SEL=0: g_h @ qkv_w + b.  bn=0 -> g_q fp32; bn=1,2 -> g_kv fp16 interleaved.
// SEL=1: g_agg @ out_w + b + x -> outparam fp32.
template<int SEL>
__global__ void k_gemm_tc(const float* __restrict__ w, const float* __restrict__ b,
                          const float* __restrict__ x, float* __restrict__ outparam) {
    constexpr int WSTRIDE = (SEL == 0) ? 384 : 128;
    const float* a_src = (SEL == 0) ? g_h : g_agg;

    __shared__ float sA[128][36];
    __shared__ float sB[32][132];
    int bm = blockIdx.x, bn = blockIdx.y;
    int tid = threadIdx.x;
    int warp = tid >> 5, lane = tid & 31;
    int wm = warp & 3;
    int wn = warp >> 2;
    int lr = lane >> 2;
    int lc = lane & 3;

    float acc[2][8][4];
    #pragma unroll
    for (int t = 0; t < 2; t++)
        #pragma unroll
        for (int n = 0; n < 8; n++)
            #pragma unroll
            for (int j = 0; j < 4; j++) acc[t][n][j] = 0.f;

    for (int k0 = 0; k0 < D_MODEL; k0 += 32) {
        #pragma unroll
        for (int i = tid; i < 128 * 8; i += 256) {
            int r = i >> 3, c4 = (i & 7) * 4;
            int gr = min(bm * 128 + r, N_NODES - 1);
            float4 v = *(const float4*)&a_src[gr * D_MODEL + k0 + c4];
            *(float4*)&sA[r][c4] = v;
        }
        #pragma unroll
        for (int i = tid; i < 32 * 32; i += 256) {
            int r = i >> 5, c4 = (i & 31) * 4;
            float4 v = *(const float4*)&w[(k0 + r) * WSTRIDE + bn * 128 + c4];
            *(float4*)&sB[r][c4] = v;
        }
        __syncthreads();
        #pragma unroll
        for (int ks = 0; ks < 4; ks++) {
            int kk = ks * 8;
            unsigned ah[2][4], al[2][4];
            #pragma unroll
            for (int t = 0; t < 2; t++) {
                int r0 = wm * 32 + t * 16 + lr;
                float f0 = sA[r0][kk + lc];
                float f1 = sA[r0 + 8][kk + lc];
                float f2 = sA[r0][kk + lc + 4];
                float f3 = sA[r0 + 8][kk + lc + 4];
                ah[t][0] = f2tf32(f0); al[t][0] = f2tf32(f0 - __uint_as_float(ah[t][0]));
                ah[t][1] = f2tf32(f1); al[t][1] = f2tf32(f1 - __uint_as_float(ah[t][1]));
                ah[t][2] = f2tf32(f2); al[t][2] = f2tf32(f2 - __uint_as_float(ah[t][2]));
                ah[t][3] = f2tf32(f3); al[t][3] = f2tf32(f3 - __uint_as_float(ah[t][3]));
            }
            #pragma unroll
            for (int n = 0; n < 8; n++) {
                int c = wn * 64 + n * 8 + lr;
                float g0 = sB[kk + lc][c];
                float g1 = sB[kk + lc + 4][c];
                unsigned bh[2], bl[2];
                bh[0] = f2tf32(g0); bl[0] = f2tf32(g0 - __uint_as_float(bh[0]));
                bh[1] = f2tf32(g1); bl[1] = f2tf32(g1 - __uint_as_float(bh[1]));
                #pragma unroll
                for (int t = 0; t < 2; t++) {
                    mma_tf32(acc[t][n], al[t], bh);
                    mma_tf32(acc[t][n], ah[t], bl);
                    mma_tf32(acc[t][n], ah[t], bh);
                }
            }
        }
        __syncthreads();
    }

    #pragma unroll
    for (int t = 0; t < 2; t++) {
        #pragma unroll
        for (int n = 0; n < 8; n++) {
            int cl = wn * 64 + n * 8 + 2 * lc;     // local col 0..127 (even)
            int c  = bn * 128 + cl;                // global col
            float b0 = b[c], b1 = b[c + 1];
            #pragma unroll
            for (int half = 0; half < 2; half++) {
                int node = bm * 128 + wm * 32 + t * 16 + lr + half * 8;
                if (node < N_NODES) {
                    float v0 = acc[t][n][half * 2]     + b0;
                    float v1 = acc[t][n][half * 2 + 1] + b1;
                    if (SEL == 1) {
                        v0 += x[node * D_MODEL + cl];
                        v1 += x[node * D_MODEL + cl + 1];
                        outparam[node * 128 + cl]     = v0;
                        outparam[node * 128 + cl + 1] = v1;
                    } else {
                        if (bn == 0) {
                            g_q[node * 128 + cl]     = v0;
                            g_q[node * 128 + cl + 1] = v1;
                        } else {
                            // interleaved kv row: group g holds halves
                            // [k(4g..4g+3) | v(4g..4g+3)] at half-index g*8
                            int grp = cl >> 2, rem = cl & 3;
                            int hidx = grp * 8 + rem + ((bn == 2) ? 4 : 0);
                            *(__half2*)&g_kv[node * 256 + hidx] =
                                __floats2half2_rn(v0, v1);
                        }
                    }
                }
            }
        }
    }
}

// ---------------- fused edge phase: fp16 kv, single 16B gather ---------------
__global__ void k_edge_fused(const float* __restrict__ ea) {
    int node = (blockIdx.x * blockDim.x + threadIdx.x) >> 5;
    if (node >= N_NODES) return;
    int lane = threadIdx.x & 31;
    int beg = g_off[node], end = g_off[node + 1];
    unsigned long long pol = mk_policy();

    float4 q4 = *(const float4*)&g_q[node * 128 + lane * 4];

    float m = -CUDART_INF_F, S = 0.f;
    float ax = 0.f, ay = 0.f, az = 0.f, aw = 0.f;

    int e = beg;
    int2 se = (e < end) ? ld_stream_i2(&g_csr[e]) : make_int2(0, 0);
    while (e < end) {
        int en = e + 1;
        int2 se_next = (en < end) ? ld_stream_i2(&g_csr[en]) : make_int2(0, 0);

        // one 16B load: 4 k-halves + 4 v-halves for this lane's dims
        uint4 kvraw = ld_resident_u4(&g_kv[(size_t)se.x * 256 + lane * 8], pol);
        float4 av = ld_stream(&ea[(size_t)se.y * D_MODEL + lane * 4]);

        const __half2* hp = (const __half2*)&kvraw;
        float2 k01 = __half22float2(hp[0]);
        float2 k23 = __half22float2(hp[1]);
        float2 v01 = __half22float2(hp[2]);
        float2 v23 = __half22float2(hp[3]);

        float p = q4.x * (k01.x + av.x) + q4.y * (k01.y + av.y)
                + q4.z * (k23.x + av.z) + q4.w * (k23.y + av.w);
        p += __shfl_xor_sync(0xFFFFFFFFu, p, 1);
        p += __shfl_xor_sync(0xFFFFFFFFu, p, 2);   // 4-lane head group shares sum
        p *= 0.25f;                                 // DH^-0.5
        float mn = fmaxf(m, p);
        float sc = __expf(m - mn);                  // first iter: exp(-inf)=0
        float ex = __expf(p - mn);
        S  = S * sc + ex;
        ax = ax * sc + ex * v01.x;
        ay = ay * sc + ex * v01.y;
        az = az * sc + ex * v23.x;
        aw = aw * sc + ex * v23.y;
        m = mn;

        se = se_next;
        e = en;
    }
    float r = 1.f / fmaxf(S, 1e-16f);
    float4 o; o.x = ax * r; o.y = ay * r; o.z = az * r; o.w = aw * r;
    if (beg == end) { o.x = 0.f; o.y = 0.f; o.z = 0.f; o.w = 0.f; }
    *(float4*)&g_agg[node * D_MODEL + lane * 4] = o;
}

// ---------------- launch -----------------------------------------------------
extern "C" void kernel_launch(void* const* d_in, const int* in_sizes, int n_in,
                              void* d_out, int out_size) {
    const float* x     = (const float*)d_in[0];
    const float* ea    = (const float*)d_in[1];
    const float* qkv_w = (const float*)d_in[2];
    const float* qkv_b = (const float*)d_in[3];
    const float* out_w = (const float*)d_in[4];
    const float* out_b = (const float*)d_in[5];
    const float* ln_g  = (const float*)d_in[6];
    const float* ln_b  = (const float*)d_in[7];
    const int*   ei    = (const int*)d_in[8];   // int32 [2, E]
    float* out = (float*)d_out;

    // CSR build
    k_zero_cnt<<<(N_NODES + 255) / 256, 256>>>();
    k_hist<<<(N_EDGES + 255) / 256, 256>>>(ei);
    k_scan<<<1, 1024>>>();
    k_scatter<<<(N_EDGES + 255) / 256, 256>>>(ei);

    // layernorm
    k_ln<<<(N_NODES + 7) / 8, 256>>>(x, ln_g, ln_b);

    // qkv gemm: 3xTF32 tensor cores, fp16 k/v emission
    {
        dim3 g((N_NODES + 127) / 128, 3);
        k_gemm_tc<0><<<g, 256>>>(qkv_w, qkv_b, nullptr, nullptr);
    }

    // fused edge phase (fp16 kv gathers)
    k_edge_fused<<<(N_NODES + 7) / 8, 256>>>(ea);

    // out gemm + bias + residual
    {
        dim3 g((N_NODES + 127) / 128, 1);
        k_gemm_tc<1><<<g, 256>>>(out_w, out_b, x, out);
    }
}